// round 7
// baseline (speedup 1.0000x reference)
#include <cuda_runtime.h>
#include <cuda_bf16.h>
#include <cstdint>

// Quantizer: per-group(128) absmax -> PoT scale -> int8 quantize -> dequantize (fused=1).
// One warp handles TWO groups of 128 floats (2 independent front-batched LDG.128
// per lane). Stores use evict-streaming (zero reuse). Kernel is HBM-roofline-bound:
// 512 MB total traffic @ ~6.35 TB/s achieved => ~75.5us kernel time.

static constexpr float Q_MAX = 127.0f;
static constexpr float Q_MIN = -128.0f;

__device__ __forceinline__ float4 qdq4(float4 v, float inv, float scale) {
    float4 o;
    o.x = fminf(fmaxf(rintf(v.x * inv), Q_MIN), Q_MAX) * scale;
    o.y = fminf(fmaxf(rintf(v.y * inv), Q_MIN), Q_MAX) * scale;
    o.z = fminf(fmaxf(rintf(v.z * inv), Q_MIN), Q_MAX) * scale;
    o.w = fminf(fmaxf(rintf(v.w * inv), Q_MIN), Q_MAX) * scale;
    return o;
}

__device__ __forceinline__ float absmax4(float4 v) {
    return fmaxf(fmaxf(fabsf(v.x), fabsf(v.y)), fmaxf(fabsf(v.z), fabsf(v.w)));
}

__device__ __forceinline__ void pot_scale(float m, int s_hi, float& inv, float& scale) {
    // scale0 = absmax/127 ; s = clip(ceil(log2(scale0)), 0, s_hi); scale = 2^s
    float scale0 = m * (1.0f / 127.0f);
    int s = (scale0 > 0.0f) ? (int)ceilf(log2f(scale0)) : 0;  // log2(0)=-inf -> clips to 0
    s = max(0, min(s_hi, s));
    scale = exp2f((float)s);        // exact power of two (fp16-exact)
    inv   = exp2f((float)(-s));     // exact reciprocal
}

__global__ void __launch_bounds__(256)
quantizer_qdq_kernel(const float4* __restrict__ in,
                     float4* __restrict__ out,
                     const int* __restrict__ w_scale_bits_p,
                     long long n_vec4)
{
    const int warps_per_block = blockDim.x >> 5;
    const long long warp_id = (long long)blockIdx.x * warps_per_block + (threadIdx.x >> 5);
    const int lane = threadIdx.x & 31;

    // Each warp owns 2 consecutive groups: float4 indices warp*64 + {lane, lane+32}
    const long long i0 = warp_id * 64 + lane;
    const long long i1 = i0 + 32;
    if (i0 >= n_vec4) return;

    const bool has1 = (i1 < n_vec4);

    // Front-batched independent loads (MLP=2), default cache path (best measured)
    const float4 v0 = in[i0];
    float4 v1 = make_float4(0.f, 0.f, 0.f, 0.f);
    if (has1) v1 = in[i1];

    const int s_hi = (1 << (w_scale_bits_p ? __ldg(w_scale_bits_p) : 3)) - 1;

    // Two independent warp max-reductions, interleaved for ILP
    float m0 = absmax4(v0);
    float m1 = absmax4(v1);
    #pragma unroll
    for (int o = 16; o > 0; o >>= 1) {
        m0 = fmaxf(m0, __shfl_xor_sync(0xFFFFFFFFu, m0, o));
        m1 = fmaxf(m1, __shfl_xor_sync(0xFFFFFFFFu, m1, o));
    }

    float inv0, sc0, inv1, sc1;
    pot_scale(m0, s_hi, inv0, sc0);
    pot_scale(m1, s_hi, inv1, sc1);

    // Evict-streaming stores: keep the write stream from churning L2
    __stcs(&out[i0], qdq4(v0, inv0, sc0));
    if (has1) __stcs(&out[i1], qdq4(v1, inv1, sc1));
}

extern "C" void kernel_launch(void* const* d_in, const int* in_sizes, int n_in,
                              void* d_out, int out_size)
{
    const float* t = (const float*)d_in[0];
    const int* w_scale_bits = (n_in >= 3) ? (const int*)d_in[2] : nullptr;

    const long long n = (long long)in_sizes[0];          // 67108864 floats
    const long long n_vec4 = n >> 2;                     // 16777216 float4s

    const int threads = 256;                             // 8 warps/block, 16 groups/block
    const int warps_per_block = threads / 32;
    const long long n_warp_units = (n_vec4 + 63) / 64;   // 2 groups (64 float4s) per warp
    const int blocks = (int)((n_warp_units + warps_per_block - 1) / warps_per_block);

    quantizer_qdq_kernel<<<blocks, threads>>>(
        (const float4*)t, (float4*)d_out, w_scale_bits, n_vec4);
}

// round 8
// speedup vs baseline: 1.1653x; 1.1653x over previous
#include <cuda_runtime.h>
#include <cuda_bf16.h>
#include <cstdint>

// Quantizer: per-group(128) absmax -> PoT scale -> int8 quantize -> dequantize (fused=1).
// One warp handles TWO groups of 128 floats (2 independent front-batched LDG.128
// per lane). Default cache policy on loads AND stores — measured best of the
// four {load,store}x{default,streaming} quadrants (6358 GB/s; __stcs stores cost
// ~20% DRAM efficiency on this full-line write stream). HBM-roofline-bound:
// 512 MB total traffic @ ~6.35 TB/s achieved => ~75.5us kernel time.

static constexpr float Q_MAX = 127.0f;
static constexpr float Q_MIN = -128.0f;

__device__ __forceinline__ float4 qdq4(float4 v, float inv, float scale) {
    float4 o;
    o.x = fminf(fmaxf(rintf(v.x * inv), Q_MIN), Q_MAX) * scale;
    o.y = fminf(fmaxf(rintf(v.y * inv), Q_MIN), Q_MAX) * scale;
    o.z = fminf(fmaxf(rintf(v.z * inv), Q_MIN), Q_MAX) * scale;
    o.w = fminf(fmaxf(rintf(v.w * inv), Q_MIN), Q_MAX) * scale;
    return o;
}

__device__ __forceinline__ float absmax4(float4 v) {
    return fmaxf(fmaxf(fabsf(v.x), fabsf(v.y)), fmaxf(fabsf(v.z), fabsf(v.w)));
}

__device__ __forceinline__ void pot_scale(float m, int s_hi, float& inv, float& scale) {
    // scale0 = absmax/127 ; s = clip(ceil(log2(scale0)), 0, s_hi); scale = 2^s
    float scale0 = m * (1.0f / 127.0f);
    int s = (scale0 > 0.0f) ? (int)ceilf(log2f(scale0)) : 0;  // log2(0)=-inf -> clips to 0
    s = max(0, min(s_hi, s));
    scale = exp2f((float)s);        // exact power of two (fp16-exact)
    inv   = exp2f((float)(-s));     // exact reciprocal
}

__global__ void __launch_bounds__(256)
quantizer_qdq_kernel(const float4* __restrict__ in,
                     float4* __restrict__ out,
                     const int* __restrict__ w_scale_bits_p,
                     long long n_vec4)
{
    const int warps_per_block = blockDim.x >> 5;
    const long long warp_id = (long long)blockIdx.x * warps_per_block + (threadIdx.x >> 5);
    const int lane = threadIdx.x & 31;

    // Each warp owns 2 consecutive groups: float4 indices warp*64 + {lane, lane+32}
    const long long i0 = warp_id * 64 + lane;
    const long long i1 = i0 + 32;
    if (i0 >= n_vec4) return;

    const bool has1 = (i1 < n_vec4);

    // Front-batched independent loads (MLP=2)
    const float4 v0 = in[i0];
    float4 v1 = make_float4(0.f, 0.f, 0.f, 0.f);
    if (has1) v1 = in[i1];

    const int s_hi = (1 << (w_scale_bits_p ? __ldg(w_scale_bits_p) : 3)) - 1;

    // Two independent warp max-reductions, interleaved for ILP
    float m0 = absmax4(v0);
    float m1 = absmax4(v1);
    #pragma unroll
    for (int o = 16; o > 0; o >>= 1) {
        m0 = fmaxf(m0, __shfl_xor_sync(0xFFFFFFFFu, m0, o));
        m1 = fmaxf(m1, __shfl_xor_sync(0xFFFFFFFFu, m1, o));
    }

    float inv0, sc0, inv1, sc1;
    pot_scale(m0, s_hi, inv0, sc0);
    pot_scale(m1, s_hi, inv1, sc1);

    // Default-policy stores (L2 write-coalescing intact)
    out[i0] = qdq4(v0, inv0, sc0);
    if (has1) out[i1] = qdq4(v1, inv1, sc1);
}

extern "C" void kernel_launch(void* const* d_in, const int* in_sizes, int n_in,
                              void* d_out, int out_size)
{
    const float* t = (const float*)d_in[0];
    const int* w_scale_bits = (n_in >= 3) ? (const int*)d_in[2] : nullptr;

    const long long n = (long long)in_sizes[0];          // 67108864 floats
    const long long n_vec4 = n >> 2;                     // 16777216 float4s

    const int threads = 256;                             // 8 warps/block, 16 groups/block
    const int warps_per_block = threads / 32;
    const long long n_warp_units = (n_vec4 + 63) / 64;   // 2 groups (64 float4s) per warp
    const int blocks = (int)((n_warp_units + warps_per_block - 1) / warps_per_block);

    quantizer_qdq_kernel<<<blocks, threads>>>(
        (const float4*)t, (float4*)d_out, w_scale_bits, n_vec4);
}